// round 3
// baseline (speedup 1.0000x reference)
#include <cuda_runtime.h>
#include <math.h>
#include <stdint.h>

#define VN 9216
#define EN 18240
#define WID 96
#define B_ 8
#define NC 21
#define H0_ 384

// ---------------- global scratch ----------------
__device__ __align__(16) float g_low[B_ * 3 * VN];
__device__ float g_prob[B_ * NC * VN];
__device__ float g_ew[16 * VN];               // indexed by node
__device__ unsigned g_ord32[16 * VN];         // rank -> v | childmask<<14 | pardir<<18
__device__ int g_tredge[16 * VN];
__device__ int g_levelstart[16 * 2048];
__device__ int g_maxd[16];
__device__ double g_partL[56];
__device__ double g_partN[B_];

__constant__ int c_off[4] = {-WID, WID, -1, 1};

__device__ __forceinline__ void edge_uv(int e, int& u, int& v) {
    if (e < 9120) { u = e; v = e + WID; }
    else { int t = e - 9120; int r = t / 95, c = t - r * 95; u = r * WID + c; v = u + 1; }
}

// ---------------- prep: antialiased bilinear resize 384->96 ----------------
__global__ void resize_kernel(const float* __restrict__ low) {
    int idx = blockIdx.x * blockDim.x + threadIdx.x;
    if (idx >= B_ * 3 * VN) return;
    int v = idx % VN;
    int bc = idx / VN;
    int oy = v / WID, ox = v - (v / WID) * WID;
    const float rw[8] = {0.125f, 0.375f, 0.625f, 0.875f, 0.875f, 0.625f, 0.375f, 0.125f};
    int iy0 = 4 * oy - 2, ix0 = 4 * ox - 2;
    float wy[8], wx[8], sy = 0.f, sx = 0.f;
#pragma unroll
    for (int j = 0; j < 8; j++) {
        int iy = iy0 + j;
        wy[j] = (iy >= 0 && iy < H0_) ? rw[j] : 0.f;
        sy += wy[j];
        int ix = ix0 + j;
        wx[j] = (ix >= 0 && ix < H0_) ? rw[j] : 0.f;
        sx += wx[j];
    }
    const float* src = low + (size_t)bc * (H0_ * H0_);
    float acc = 0.f;
#pragma unroll
    for (int j = 0; j < 8; j++) {
        if (wy[j] == 0.f) continue;
        const float* row = src + (iy0 + j) * H0_;
        float rs = 0.f;
#pragma unroll
        for (int k = 0; k < 8; k++) {
            if (wx[k] != 0.f) rs += wx[k] * row[ix0 + k];
        }
        acc += wy[j] * rs;
    }
    g_low[idx] = acc / (sy * sx);
}

// ---------------- prep: softmax ----------------
__global__ void softmax_kernel(const float* __restrict__ preds) {
    int idx = blockIdx.x * blockDim.x + threadIdx.x;
    if (idx >= B_ * VN) return;
    int b = idx / VN, v = idx - (idx / VN) * VN;
    const float* p = preds + (size_t)b * NC * VN + v;
    float vals[NC];
    float m = -3.4e38f;
#pragma unroll
    for (int c = 0; c < NC; c++) { vals[c] = p[(size_t)c * VN]; m = fmaxf(m, vals[c]); }
    float s = 0.f;
#pragma unroll
    for (int c = 0; c < NC; c++) { vals[c] = expf(vals[c] - m); s += vals[c]; }
    float inv = 1.f / s;
    float* o = g_prob + (size_t)b * NC * VN + v;
#pragma unroll
    for (int c = 0; c < NC; c++) o[(size_t)c * VN] = vals[c] * inv;
}

// ---------------- one-warp BFS pass over the tree ----------------
// qS: order queue (u16), par16: parent (u16, 0xFFFF for root), lsS: level starts.
// In a tree, any neighbor except the parent is an unvisited child -> no visited
// array, no atomics; append via warp ballot prefix (deterministic).
__device__ __forceinline__ int bfs_pass(unsigned short* qS, unsigned short* par16,
                                        int* lsS, const int* adjS, int root,
                                        int lane, bool needLs, int& farOut) {
    if (lane == 0) {
        qS[0] = (unsigned short)root;
        par16[root] = 0xFFFFu;
        if (needLs) { lsS[0] = 0; lsS[1] = 1; }
    }
    __syncwarp();
    int fs = 0, fe = 1, level = 0;
    while (true) {
        int cur = fe;
        for (int i0 = fs; i0 < fe; i0 += 32) {
            int i = i0 + lane;
            int cnt = 0; int ch[4]; int v = 0;
            if (i < fe) {
                v = qS[i];
                int m = adjS[v];
                int par = par16[v];
                int delta = par - v;
                int pb = (delta == -WID) ? 1 : (delta == WID) ? 2 : (delta == -1) ? 4 : (delta == 1) ? 8 : 0;
                m &= ~pb;
                while (m) { int dd = __ffs(m) - 1; m &= m - 1; ch[cnt++] = v + c_off[dd]; }
            }
            int pre = cnt;
#pragma unroll
            for (int o = 1; o < 32; o <<= 1) {
                int tt = __shfl_up_sync(0xFFFFFFFFu, pre, o);
                if (lane >= o) pre += tt;
            }
            int tot = __shfl_sync(0xFFFFFFFFu, pre, 31);
            int pos = cur + pre - cnt;
            for (int k = 0; k < cnt; k++) {
                qS[pos + k] = (unsigned short)ch[k];
                par16[ch[k]] = (unsigned short)v;
            }
            cur += tot;
        }
        __syncwarp();
        if (cur == fe) break;
        level++;
        if (needLs && lane == 0) lsS[level + 1] = cur;
        fs = fe; fe = cur;
    }
    farOut = qS[fe - 1];
    return level;
}

// ---------------- tree build ----------------
// smem layout:
//   [0,73728)        bestS u64[VN]      | post: qS u16[VN] @0, par16 u16[VN] @18432
//   [73728,146688)   wS float[EN]       (alive until export)
//   [146688,183552)  compS int[VN]      | post: lsS int[1024] @146688
//   [183552,220416)  linkS int[VN]      | post: adjS int[VN]
#define BUILD_SMEM 220416

extern "C" __global__ void __launch_bounds__(1024, 1)
build_kernel(const float* __restrict__ high) {
    extern __shared__ unsigned char sm[];
    int t = blockIdx.x;
    int b = t >> 1, f = t & 1;
    const float* embed = f ? (high + (size_t)b * 256 * VN) : ((const float*)g_low + (size_t)b * 3 * VN);
    int C = f ? 256 : 3;

    unsigned long long* bestS = (unsigned long long*)sm;
    float* wS = (float*)(sm + 73728);
    int* compS = (int*)(sm + 146688);
    int* linkS = (int*)(sm + 183552);
    unsigned short* qS = (unsigned short*)sm;
    unsigned short* par16 = (unsigned short*)(sm + 18432);
    int* lsS = (int*)(sm + 146688);
    int* adjS = (int*)(sm + 183552);

    __shared__ int sFlag, sCnt, sRoot, sMaxd;
    int tid = threadIdx.x;
    const int NT = 1024;

    // ---- 1. edge weights: 3-row bands with float4 loads ----
    if (tid < 768) {
        int t0 = tid % 24, band = tid / 24;
        int c0 = t0 * 4, r0 = band * 3;
        bool hasR3 = (band < 31);
        bool hasS = (t0 < 23);
        float aV[3][4], aH[3][4];
#pragma unroll
        for (int j = 0; j < 3; j++)
#pragma unroll
            for (int k = 0; k < 4; k++) { aV[j][k] = 0.f; aH[j][k] = 0.f; }
        for (int c = 0; c < C; ++c) {
            const float* pf = embed + (size_t)c * VN;
            const float4* p4 = (const float4*)pf;
            float4 q0 = p4[(r0 + 0) * 24 + t0];
            float4 q1 = p4[(r0 + 1) * 24 + t0];
            float4 q2 = p4[(r0 + 2) * 24 + t0];
            float4 q3 = hasR3 ? p4[(r0 + 3) * 24 + t0] : make_float4(0.f, 0.f, 0.f, 0.f);
            float rr[4][4];
            rr[0][0]=q0.x; rr[0][1]=q0.y; rr[0][2]=q0.z; rr[0][3]=q0.w;
            rr[1][0]=q1.x; rr[1][1]=q1.y; rr[1][2]=q1.z; rr[1][3]=q1.w;
            rr[2][0]=q2.x; rr[2][1]=q2.y; rr[2][2]=q2.z; rr[2][3]=q2.w;
            rr[3][0]=q3.x; rr[3][1]=q3.y; rr[3][2]=q3.z; rr[3][3]=q3.w;
            float s0 = 0.f, s1 = 0.f, s2 = 0.f;
            if (hasS) {
                s0 = pf[(r0 + 0) * WID + c0 + 4];
                s1 = pf[(r0 + 1) * WID + c0 + 4];
                s2 = pf[(r0 + 2) * WID + c0 + 4];
            }
            float ss[3] = {s0, s1, s2};
#pragma unroll
            for (int j = 0; j < 3; j++) {
#pragma unroll
                for (int k = 0; k < 4; k++) {
                    float dv = rr[j][k] - rr[j + 1][k];
                    aV[j][k] += dv * dv;
                }
#pragma unroll
                for (int k = 0; k < 3; k++) {
                    float dh = rr[j][k] - rr[j][k + 1];
                    aH[j][k] += dh * dh;
                }
                if (hasS) { float dh = rr[j][3] - ss[j]; aH[j][3] += dh * dh; }
            }
        }
#pragma unroll
        for (int j = 0; j < 3; j++) {
            int r = r0 + j;
            if (r < 95) {
#pragma unroll
                for (int k = 0; k < 4; k++) wS[r * WID + c0 + k] = aV[j][k];
            }
            int hb = 9120 + r * 95 + c0;
            wS[hb + 0] = aH[j][0]; wS[hb + 1] = aH[j][1]; wS[hb + 2] = aH[j][2];
            if (hasS) wS[hb + 3] = aH[j][3];
        }
    }
    for (int v = tid; v < VN; v += NT) compS[v] = v;
    if (tid == 0) sCnt = 0;
    __syncthreads();

    // ---- 2. Boruvka ((w_bits, e) keys == stable-Kruskal tree) ----
    for (int round = 0; round < 20; ++round) {
        for (int v = tid; v < VN; v += NT) bestS[v] = ~0ull;
        if (tid == 0) sFlag = 0;
        __syncthreads();
        for (int e = tid; e < EN; e += NT) {
            int u, v; edge_uv(e, u, v);
            int cu = compS[u], cv = compS[v];
            if (cu != cv) {
                unsigned long long key = ((unsigned long long)__float_as_uint(wS[e]) << 32) | (unsigned)e;
                atomicMin(&bestS[cu], key);
                atomicMin(&bestS[cv], key);
                sFlag = 1;
            }
        }
        __syncthreads();
        if (!sFlag) break;
        // hook roots along best edge; record tree edges (dedup)
        for (int v = tid; v < VN; v += NT) {
            unsigned long long bk = bestS[v];
            int nl = v;
            if (bk != ~0ull) {
                int e = (int)(bk & 0xffffffffu);
                int u0, v0; edge_uv(e, u0, v0);
                int cu = compS[u0], cv = compS[v0];
                int d = (cu == v) ? cv : cu;
                nl = d;
                if (bestS[d] != bk || v < d) {
                    int p = atomicAdd(&sCnt, 1);
                    g_tredge[t * VN + p] = e;
                }
            }
            linkS[v] = nl;
        }
        __syncthreads();
        {   // break 2-cycles (only cycles possible under distinct keys)
            int nl[9]; int ki = 0;
            for (int v = tid; v < VN; v += NT, ++ki) {
                int l = linkS[v];
                nl[ki] = (l != v && linkS[l] == v && v < l) ? v : l;
            }
            __syncthreads();
            ki = 0;
            for (int v = tid; v < VN; v += NT, ++ki) linkS[v] = nl[ki];
            __syncthreads();
        }
        // per-thread root chase (no synchronized pointer jumping)
        for (int v = tid; v < VN; v += NT) {
            int r = compS[v];
            int l = linkS[r];
            while (l != r) { r = l; l = linkS[r]; }
            compS[v] = r;
        }
        __syncthreads();
    }
    __syncthreads();
    int nTree = sCnt;

    // ---- 3. tree adjacency masks (bit0:-96 bit1:+96 bit2:-1 bit3:+1) ----
    for (int v = tid; v < VN; v += NT) adjS[v] = 0;
    __syncthreads();
    for (int i = tid; i < nTree; i += NT) {
        int e = g_tredge[t * VN + i];
        int u, v; edge_uv(e, u, v);
        if (e < 9120) { atomicOr(&adjS[u], 2); atomicOr(&adjS[v], 1); }
        else { atomicOr(&adjS[u], 8); atomicOr(&adjS[v], 4); }
    }
    __syncthreads();

    // ---- 4. center rooting: double-BFS for diameter, then final BFS from center ----
    // (tree filter result is root-invariant; center minimizes depth => fewer
    //  sequential levels in the sweeps)
    if (tid < 32) {
        int far1, far2, far3;
        bfs_pass(qS, par16, lsS, adjS, 0, tid, false, far1);
        int diam = bfs_pass(qS, par16, lsS, adjS, far1, tid, false, far2);
        if (tid == 0) {
            int c = far2;
            for (int k = 0; k < diam / 2; k++) c = par16[c];
            sRoot = c;
        }
        __syncwarp();
        int maxd = bfs_pass(qS, par16, lsS, adjS, sRoot, tid, true, far3);
        if (tid == 0) sMaxd = maxd;
    }
    __syncthreads();
    int maxd = sMaxd;

    // ---- 5. export packed structure; ew from wS (tree edges ARE grid edges) ----
    for (int pos = tid; pos < VN; pos += NT) {
        int v = qS[pos];
        int par = par16[v];
        int m = adjS[v];
        int pardir = 0, cm = m;
        float ew = 0.f;
        if (par != 0xFFFF) {
            int delta = par - v;
            pardir = (delta == -WID) ? 0 : (delta == WID) ? 1 : (delta == -1) ? 2 : 3;
            cm = m & ~(1 << pardir);
            int mn = v < par ? v : par;
            int ad = delta < 0 ? -delta : delta;
            int e = (ad == WID) ? mn : 9120 + (mn / WID) * 95 + (mn - (mn / WID) * WID);
            ew = expf(-wS[e] * 0.5f);
        }
        g_ord32[t * VN + pos] = (unsigned)v | ((unsigned)cm << 14) | ((unsigned)pardir << 18);
        g_ew[t * VN + v] = ew;
    }
    for (int d = tid; d <= maxd + 1; d += NT) g_levelstart[t * 2048 + d] = lsS[d];
    if (tid == 0) g_maxd[t] = maxd;
}

// ---------------- fused two-filter sweep + loss partial ----------------
// smem: buf float4[VN] @0 (147456) | ewS f32[VN] @147456 | ordS u32[VN] @184320
//       | lsS int[1024] @221184 ; loss sred doubles reuse ewS region at the end
#define SWEEP_SMEM 225280

extern "C" __global__ void __launch_bounds__(256, 1)
sweep_kernel(const int* __restrict__ roi) {
    extern __shared__ unsigned char sm[];
    float4* buf = (float4*)sm;
    float* ewS = (float*)(sm + 147456);
    unsigned* ordS = (unsigned*)(sm + 184320);
    int* lsS = (int*)(sm + 221184);
    double* sredL = (double*)(sm + 147456);
    double* sredN = (double*)(sm + 147456 + 2048);
    int g = blockIdx.x, b = blockIdx.y;
    int tid = threadIdx.x;
    const int NT = 256;

    const float* pr0 = g_prob + ((size_t)b * NC + 3 * g) * VN;
    for (int v = tid; v < VN; v += NT)
        buf[v] = make_float4(pr0[v], pr0[v + VN], pr0[v + 2 * VN], 1.f);

    int maxd;
    for (int f = 0; f < 2; f++) {
        int t = b * 2 + f;
        maxd = g_maxd[t];
        for (int v = tid; v < VN; v += NT) {
            ewS[v] = g_ew[t * VN + v];
            ordS[v] = g_ord32[t * VN + v];
        }
        for (int d = tid; d <= maxd + 1; d += NT) lsS[d] = g_levelstart[t * 2048 + d];
        __syncthreads();

        if (tid < 64) {
            // up sweep (pull from children; fixed direction order)
            int hi = lsS[maxd];
            for (int d = maxd - 1; d >= 0; --d) {
                int lo = lsS[d];
                for (int i = lo + tid; i < hi; i += 64) {
                    unsigned o = ordS[i];
                    int v = o & 0x3FFF;
                    int cm = (o >> 14) & 0xF;
                    float4 acc = buf[v];
                    if (cm & 1) { int ch = v - WID; float w = ewS[ch]; float4 cb = buf[ch];
                        acc.x = fmaf(w, cb.x, acc.x); acc.y = fmaf(w, cb.y, acc.y);
                        acc.z = fmaf(w, cb.z, acc.z); acc.w = fmaf(w, cb.w, acc.w); }
                    if (cm & 2) { int ch = v + WID; float w = ewS[ch]; float4 cb = buf[ch];
                        acc.x = fmaf(w, cb.x, acc.x); acc.y = fmaf(w, cb.y, acc.y);
                        acc.z = fmaf(w, cb.z, acc.z); acc.w = fmaf(w, cb.w, acc.w); }
                    if (cm & 4) { int ch = v - 1; float w = ewS[ch]; float4 cb = buf[ch];
                        acc.x = fmaf(w, cb.x, acc.x); acc.y = fmaf(w, cb.y, acc.y);
                        acc.z = fmaf(w, cb.z, acc.z); acc.w = fmaf(w, cb.w, acc.w); }
                    if (cm & 8) { int ch = v + 1; float w = ewS[ch]; float4 cb = buf[ch];
                        acc.x = fmaf(w, cb.x, acc.x); acc.y = fmaf(w, cb.y, acc.y);
                        acc.z = fmaf(w, cb.z, acc.z); acc.w = fmaf(w, cb.w, acc.w); }
                    buf[v] = acc;
                }
                hi = lo;
                asm volatile("bar.sync 1, 64;" ::: "memory");
            }
            // down sweep (in place)
            int lo2 = lsS[1];
            for (int d = 1; d <= maxd; ++d) {
                int hi2 = lsS[d + 1];
                for (int i = lo2 + tid; i < hi2; i += 64) {
                    unsigned o = ordS[i];
                    int v = o & 0x3FFF;
                    int pd = (o >> 18) & 3;
                    int par = v + c_off[pd];
                    float w = ewS[v];
                    float c1 = 1.f - w * w;
                    float4 pv = buf[par];
                    float4 sv = buf[v];
                    sv.x = fmaf(w, pv.x, c1 * sv.x);
                    sv.y = fmaf(w, pv.y, c1 * sv.y);
                    sv.z = fmaf(w, pv.z, c1 * sv.z);
                    sv.w = fmaf(w, pv.w, c1 * sv.w);
                    buf[v] = sv;
                }
                lo2 = hi2;
                asm volatile("bar.sync 1, 64;" ::: "memory");
            }
        }
        __syncthreads();

        if (f == 0) {
            for (int v = tid; v < VN; v += NT) {
                float4 s = buf[v];
                buf[v] = make_float4(s.x / s.w, s.y / s.w, s.z / s.w, 1.f);
            }
            __syncthreads();
        }
    }

    // ---- loss partial: sum roi * |prob - AS| over this block's 3 channels ----
    const int* roiB = roi + (size_t)b * (H0_ * H0_);
    double aL = 0.0, aN = 0.0;
    for (int v = tid; v < VN; v += NT) {
        float4 s = buf[v];
        float ax = pr0[v] - s.x / s.w;
        float ay = pr0[v + VN] - s.y / s.w;
        float az = pr0[v + 2 * VN] - s.z / s.w;
        int y = v / WID, x = v - y * WID;
        float rv = (float)roiB[(y * 4) * H0_ + x * 4];
        aL += (double)(rv * (fabsf(ax) + fabsf(ay) + fabsf(az)));
        if (g == 0) aN += (double)rv;
    }
    sredL[tid] = aL; sredN[tid] = aN;
    __syncthreads();
    for (int s = 128; s > 0; s >>= 1) {
        if (tid < s) { sredL[tid] += sredL[tid + s]; sredN[tid] += sredN[tid + s]; }
        __syncthreads();
    }
    if (tid == 0) {
        g_partL[b * 7 + g] = sredL[0];
        if (g == 0) g_partN[b] = sredN[0];
    }
}

// ---------------- final loss ----------------
__global__ void loss_final_kernel(float* out) {
    if (threadIdx.x == 0 && blockIdx.x == 0) {
        double L = 0.0, N = 0.0;
        for (int i = 0; i < 56; i++) L += g_partL[i];
        for (int i = 0; i < B_; i++) N += g_partN[i];
        double res = (N > 0.0) ? L / ((N > 1.0) ? N : 1.0) : L;
        out[0] = (float)(0.4 * res);
    }
}

// ---------------- launch ----------------
extern "C" void kernel_launch(void* const* d_in, const int* in_sizes, int n_in,
                              void* d_out, int out_size) {
    (void)in_sizes; (void)n_in; (void)out_size;
    const float* preds = (const float*)d_in[0];
    const float* low = (const float*)d_in[1];
    const float* high = (const float*)d_in[2];
    const int* roi = (const int*)d_in[3];
    float* out = (float*)d_out;

    cudaFuncSetAttribute(build_kernel, cudaFuncAttributeMaxDynamicSharedMemorySize, BUILD_SMEM);
    cudaFuncSetAttribute(sweep_kernel, cudaFuncAttributeMaxDynamicSharedMemorySize, SWEEP_SMEM);

    resize_kernel<<<(B_ * 3 * VN + 255) / 256, 256>>>(low);
    softmax_kernel<<<(B_ * VN + 255) / 256, 256>>>(preds);
    build_kernel<<<16, 1024, BUILD_SMEM>>>(high);
    dim3 gs(7, B_);
    sweep_kernel<<<gs, 256, SWEEP_SMEM>>>(roi);
    loss_final_kernel<<<1, 1>>>(out);
}

// round 4
// speedup vs baseline: 1.7990x; 1.7990x over previous
#include <cuda_runtime.h>
#include <math.h>
#include <stdint.h>

#define VN 9216
#define EN 18240
#define WID 96
#define B_ 8
#define NC 21
#define H0_ 384
#define ROOTV 4656   /* grid center 48*96+48 — heuristic tree-center root */

// ---------------- global scratch ----------------
__device__ __align__(16) float g_low[B_ * 3 * VN];
__device__ float g_prob[B_ * NC * VN];
__device__ float g_ew[16 * VN];               // indexed by node
__device__ unsigned g_ord32[16 * VN];         // rank -> v | childmask<<14 | pardir<<18
__device__ int g_tredge[16 * VN];
__device__ int g_levelstart[16 * 2048];
__device__ int g_maxd[16];
__device__ double g_partL[56];
__device__ double g_partN[B_];

__constant__ int c_off[4] = {-WID, WID, -1, 1};

__device__ __forceinline__ void edge_uv(int e, int& u, int& v) {
    if (e < 9120) { u = e; v = e + WID; }
    else { int t = e - 9120; int r = t / 95, c = t - r * 95; u = r * WID + c; v = u + 1; }
}

// ---------------- prep: antialiased bilinear resize 384->96 ----------------
__global__ void resize_kernel(const float* __restrict__ low) {
    int idx = blockIdx.x * blockDim.x + threadIdx.x;
    if (idx >= B_ * 3 * VN) return;
    int v = idx % VN;
    int bc = idx / VN;
    int oy = v / WID, ox = v - (v / WID) * WID;
    const float rw[8] = {0.125f, 0.375f, 0.625f, 0.875f, 0.875f, 0.625f, 0.375f, 0.125f};
    int iy0 = 4 * oy - 2, ix0 = 4 * ox - 2;
    float wy[8], wx[8], sy = 0.f, sx = 0.f;
#pragma unroll
    for (int j = 0; j < 8; j++) {
        int iy = iy0 + j;
        wy[j] = (iy >= 0 && iy < H0_) ? rw[j] : 0.f;
        sy += wy[j];
        int ix = ix0 + j;
        wx[j] = (ix >= 0 && ix < H0_) ? rw[j] : 0.f;
        sx += wx[j];
    }
    const float* src = low + (size_t)bc * (H0_ * H0_);
    float acc = 0.f;
#pragma unroll
    for (int j = 0; j < 8; j++) {
        if (wy[j] == 0.f) continue;
        const float* row = src + (iy0 + j) * H0_;
        float rs = 0.f;
#pragma unroll
        for (int k = 0; k < 8; k++) {
            if (wx[k] != 0.f) rs += wx[k] * row[ix0 + k];
        }
        acc += wy[j] * rs;
    }
    g_low[idx] = acc / (sy * sx);
}

// ---------------- prep: softmax ----------------
__global__ void softmax_kernel(const float* __restrict__ preds) {
    int idx = blockIdx.x * blockDim.x + threadIdx.x;
    if (idx >= B_ * VN) return;
    int b = idx / VN, v = idx - (idx / VN) * VN;
    const float* p = preds + (size_t)b * NC * VN + v;
    float vals[NC];
    float m = -3.4e38f;
#pragma unroll
    for (int c = 0; c < NC; c++) { vals[c] = p[(size_t)c * VN]; m = fmaxf(m, vals[c]); }
    float s = 0.f;
#pragma unroll
    for (int c = 0; c < NC; c++) { vals[c] = expf(vals[c] - m); s += vals[c]; }
    float inv = 1.f / s;
    float* o = g_prob + (size_t)b * NC * VN + v;
#pragma unroll
    for (int c = 0; c < NC; c++) o[(size_t)c * VN] = vals[c] * inv;
}

// ---------------- tree build ----------------
// smem layout:
//   [0,73728)        bestS u64[VN]      | post: qS u16[VN] @0, par16 u16[VN] @18432
//   [73728,146688)   wS float[EN]       (alive until export)
//   [146688,183552)  compS int[VN]      | post: lsS int[1024] @146688
//   [183552,220416)  linkS int[VN]      | post: adjS int[VN]
#define BUILD_SMEM 220416

extern "C" __global__ void __launch_bounds__(1024, 1)
build_kernel(const float* __restrict__ high) {
    extern __shared__ unsigned char sm[];
    int t = blockIdx.x;
    int b = t >> 1, f = t & 1;
    const float* embed = f ? (high + (size_t)b * 256 * VN) : ((const float*)g_low + (size_t)b * 3 * VN);
    int C = f ? 256 : 3;

    unsigned long long* bestS = (unsigned long long*)sm;
    float* wS = (float*)(sm + 73728);
    int* compS = (int*)(sm + 146688);
    int* linkS = (int*)(sm + 183552);
    unsigned short* qS = (unsigned short*)sm;
    unsigned short* par16 = (unsigned short*)(sm + 18432);
    int* lsS = (int*)(sm + 146688);
    int* adjS = (int*)(sm + 183552);

    __shared__ int sFlag, sCnt, sCur;
    int tid = threadIdx.x;
    const int NT = 1024;

    // ---- 1. edge weights: 3-row bands with float4 loads ----
    if (tid < 768) {
        int t0 = tid % 24, band = tid / 24;
        int c0 = t0 * 4, r0 = band * 3;
        bool hasR3 = (band < 31);
        bool hasS = (t0 < 23);
        float aV[3][4], aH[3][4];
#pragma unroll
        for (int j = 0; j < 3; j++)
#pragma unroll
            for (int k = 0; k < 4; k++) { aV[j][k] = 0.f; aH[j][k] = 0.f; }
        for (int c = 0; c < C; ++c) {
            const float* pf = embed + (size_t)c * VN;
            const float4* p4 = (const float4*)pf;
            float4 q0 = p4[(r0 + 0) * 24 + t0];
            float4 q1 = p4[(r0 + 1) * 24 + t0];
            float4 q2 = p4[(r0 + 2) * 24 + t0];
            float4 q3 = hasR3 ? p4[(r0 + 3) * 24 + t0] : make_float4(0.f, 0.f, 0.f, 0.f);
            float rr[4][4];
            rr[0][0]=q0.x; rr[0][1]=q0.y; rr[0][2]=q0.z; rr[0][3]=q0.w;
            rr[1][0]=q1.x; rr[1][1]=q1.y; rr[1][2]=q1.z; rr[1][3]=q1.w;
            rr[2][0]=q2.x; rr[2][1]=q2.y; rr[2][2]=q2.z; rr[2][3]=q2.w;
            rr[3][0]=q3.x; rr[3][1]=q3.y; rr[3][2]=q3.z; rr[3][3]=q3.w;
            float s0 = 0.f, s1 = 0.f, s2 = 0.f;
            if (hasS) {
                s0 = pf[(r0 + 0) * WID + c0 + 4];
                s1 = pf[(r0 + 1) * WID + c0 + 4];
                s2 = pf[(r0 + 2) * WID + c0 + 4];
            }
            float ss[3] = {s0, s1, s2};
#pragma unroll
            for (int j = 0; j < 3; j++) {
#pragma unroll
                for (int k = 0; k < 4; k++) {
                    float dv = rr[j][k] - rr[j + 1][k];
                    aV[j][k] += dv * dv;
                }
#pragma unroll
                for (int k = 0; k < 3; k++) {
                    float dh = rr[j][k] - rr[j][k + 1];
                    aH[j][k] += dh * dh;
                }
                if (hasS) { float dh = rr[j][3] - ss[j]; aH[j][3] += dh * dh; }
            }
        }
#pragma unroll
        for (int j = 0; j < 3; j++) {
            int r = r0 + j;
            if (r < 95) {
#pragma unroll
                for (int k = 0; k < 4; k++) wS[r * WID + c0 + k] = aV[j][k];
            }
            int hb = 9120 + r * 95 + c0;
            wS[hb + 0] = aH[j][0]; wS[hb + 1] = aH[j][1]; wS[hb + 2] = aH[j][2];
            if (hasS) wS[hb + 3] = aH[j][3];
        }
    }
    for (int v = tid; v < VN; v += NT) compS[v] = v;
    if (tid == 0) sCnt = 0;
    __syncthreads();

    // ---- 2. Boruvka, vertex-gather form ((w_bits,e) keys == stable-Kruskal) ----
    // Each vertex takes the min key over its <=4 incident CROSS edges, then
    // issues ONE atomicMin into its component root (round 0: direct store).
    for (int round = 0; round < 30; ++round) {
        for (int v = tid; v < VN; v += NT) bestS[v] = ~0ull;
        if (tid == 0) sFlag = 0;
        __syncthreads();
        for (int v = tid; v < VN; v += NT) {
            int cv = compS[v];
            int r = v / WID, c = v - r * WID;
            unsigned long long best = ~0ull;
            if (r > 0 && compS[v - WID] != cv) {
                int e = v - WID;
                unsigned long long k = ((unsigned long long)__float_as_uint(wS[e]) << 32) | (unsigned)e;
                if (k < best) best = k;
            }
            if (r < 95 && compS[v + WID] != cv) {
                int e = v;
                unsigned long long k = ((unsigned long long)__float_as_uint(wS[e]) << 32) | (unsigned)e;
                if (k < best) best = k;
            }
            if (c > 0 && compS[v - 1] != cv) {
                int e = 9120 + r * 95 + c - 1;
                unsigned long long k = ((unsigned long long)__float_as_uint(wS[e]) << 32) | (unsigned)e;
                if (k < best) best = k;
            }
            if (c < 95 && compS[v + 1] != cv) {
                int e = 9120 + r * 95 + c;
                unsigned long long k = ((unsigned long long)__float_as_uint(wS[e]) << 32) | (unsigned)e;
                if (k < best) best = k;
            }
            if (best != ~0ull) {
                if (round == 0) bestS[v] = best;
                else atomicMin(&bestS[cv], best);
                sFlag = 1;
            }
        }
        __syncthreads();
        if (!sFlag) break;
        // hook roots along best edge; record tree edges (dedup: mutual pair once)
        for (int v = tid; v < VN; v += NT) {
            unsigned long long bk = bestS[v];
            int nl = v;
            if (bk != ~0ull) {
                int e = (int)(bk & 0xffffffffu);
                int u0, v0; edge_uv(e, u0, v0);
                int cu = compS[u0], cv = compS[v0];
                int d = (cu == v) ? cv : cu;
                nl = d;
                if (bestS[d] != bk || v < d) {
                    int p = atomicAdd(&sCnt, 1);
                    g_tredge[t * VN + p] = e;
                }
            }
            linkS[v] = nl;
        }
        __syncthreads();
        {   // break 2-cycles (only cycles possible under distinct keys)
            int nl[9]; int ki = 0;
            for (int v = tid; v < VN; v += NT, ++ki) {
                int l = linkS[v];
                nl[ki] = (l != v && linkS[l] == v && v < l) ? v : l;
            }
            __syncthreads();
            ki = 0;
            for (int v = tid; v < VN; v += NT, ++ki) linkS[v] = nl[ki];
            __syncthreads();
        }
        // per-thread root chase
        for (int v = tid; v < VN; v += NT) {
            int r = compS[v];
            int l = linkS[r];
            while (l != r) { r = l; l = linkS[r]; }
            compS[v] = r;
        }
        __syncthreads();
    }
    __syncthreads();
    int nTree = sCnt;

    // ---- 3. tree adjacency masks (bit0:-96 bit1:+96 bit2:-1 bit3:+1) ----
    for (int v = tid; v < VN; v += NT) adjS[v] = 0;
    __syncthreads();
    for (int i = tid; i < nTree; i += NT) {
        int e = g_tredge[t * VN + i];
        int u, v; edge_uv(e, u, v);
        if (e < 9120) { atomicOr(&adjS[u], 2); atomicOr(&adjS[v], 1); }
        else { atomicOr(&adjS[u], 8); atomicOr(&adjS[v], 4); }
    }
    __syncthreads();

    // ---- 4. frontier BFS from grid-center root (1024 threads, atomicAdd cursor).
    //      Tree filter is root-invariant; center root ~halves sweep depth. ----
    if (tid == 0) {
        qS[0] = (unsigned short)ROOTV;
        par16[ROOTV] = 0xFFFFu;
        sCur = 1;
        lsS[0] = 0; lsS[1] = 1;
    }
    __syncthreads();
    int fs = 0, fe = 1, level = 0;
    while (true) {
        for (int i = fs + tid; i < fe; i += NT) {
            int v = qS[i];
            int par = par16[v];
            int delta = par - v;
            int pb = (delta == -WID) ? 1 : (delta == WID) ? 2 : (delta == -1) ? 4 : (delta == 1) ? 8 : 0;
            int m = adjS[v] & ~pb;
            while (m) {
                int dd = __ffs(m) - 1; m &= m - 1;
                int nb = v + c_off[dd];
                par16[nb] = (unsigned short)v;
                int pos = atomicAdd(&sCur, 1);
                qS[pos] = (unsigned short)nb;
            }
        }
        __syncthreads();
        int nc2 = sCur;
        __syncthreads();
        if (nc2 == fe) break;
        level++;
        if (tid == 0) lsS[level + 1] = nc2;
        fs = fe; fe = nc2;
    }
    int maxd = level;

    // ---- 5. export packed structure; ew from wS (tree edges ARE grid edges) ----
    for (int pos = tid; pos < VN; pos += NT) {
        int v = qS[pos];
        int par = par16[v];
        int m = adjS[v];
        int pardir = 0, cm = m;
        float ew = 0.f;
        if (par != 0xFFFF) {
            int delta = par - v;
            pardir = (delta == -WID) ? 0 : (delta == WID) ? 1 : (delta == -1) ? 2 : 3;
            cm = m & ~(1 << pardir);
            int mn = v < par ? v : par;
            int ad = delta < 0 ? -delta : delta;
            int e = (ad == WID) ? mn : 9120 + (mn / WID) * 95 + (mn - (mn / WID) * WID);
            ew = expf(-wS[e] * 0.5f);
        }
        g_ord32[t * VN + pos] = (unsigned)v | ((unsigned)cm << 14) | ((unsigned)pardir << 18);
        g_ew[t * VN + v] = ew;
    }
    for (int d = tid; d <= maxd + 1; d += NT) g_levelstart[t * 2048 + d] = lsS[d];
    if (tid == 0) g_maxd[t] = maxd;
}

// ---------------- fused two-filter sweep + loss partial ----------------
// smem: buf float4[VN] @0 (147456) | ewS f32[VN] @147456 | ordS u32[VN] @184320
//       | lsS int[1024] @221184 ; loss sred doubles reuse ewS region at the end
#define SWEEP_SMEM 225280

extern "C" __global__ void __launch_bounds__(256, 1)
sweep_kernel(const int* __restrict__ roi) {
    extern __shared__ unsigned char sm[];
    float4* buf = (float4*)sm;
    float* ewS = (float*)(sm + 147456);
    unsigned* ordS = (unsigned*)(sm + 184320);
    int* lsS = (int*)(sm + 221184);
    double* sredL = (double*)(sm + 147456);
    double* sredN = (double*)(sm + 147456 + 2048);
    int g = blockIdx.x, b = blockIdx.y;
    int tid = threadIdx.x;
    const int NT = 256;

    const float* pr0 = g_prob + ((size_t)b * NC + 3 * g) * VN;
    for (int v = tid; v < VN; v += NT)
        buf[v] = make_float4(pr0[v], pr0[v + VN], pr0[v + 2 * VN], 1.f);

    int maxd;
    for (int f = 0; f < 2; f++) {
        int t = b * 2 + f;
        maxd = g_maxd[t];
        for (int v = tid; v < VN; v += NT) {
            ewS[v] = g_ew[t * VN + v];
            ordS[v] = g_ord32[t * VN + v];
        }
        for (int d = tid; d <= maxd + 1; d += NT) lsS[d] = g_levelstart[t * 2048 + d];
        __syncthreads();

        if (tid < 64) {
            // up sweep (pull from children; fixed direction order)
            int hi = lsS[maxd];
            for (int d = maxd - 1; d >= 0; --d) {
                int lo = lsS[d];
                for (int i = lo + tid; i < hi; i += 64) {
                    unsigned o = ordS[i];
                    int v = o & 0x3FFF;
                    int cm = (o >> 14) & 0xF;
                    float4 acc = buf[v];
                    if (cm & 1) { int ch = v - WID; float w = ewS[ch]; float4 cb = buf[ch];
                        acc.x = fmaf(w, cb.x, acc.x); acc.y = fmaf(w, cb.y, acc.y);
                        acc.z = fmaf(w, cb.z, acc.z); acc.w = fmaf(w, cb.w, acc.w); }
                    if (cm & 2) { int ch = v + WID; float w = ewS[ch]; float4 cb = buf[ch];
                        acc.x = fmaf(w, cb.x, acc.x); acc.y = fmaf(w, cb.y, acc.y);
                        acc.z = fmaf(w, cb.z, acc.z); acc.w = fmaf(w, cb.w, acc.w); }
                    if (cm & 4) { int ch = v - 1; float w = ewS[ch]; float4 cb = buf[ch];
                        acc.x = fmaf(w, cb.x, acc.x); acc.y = fmaf(w, cb.y, acc.y);
                        acc.z = fmaf(w, cb.z, acc.z); acc.w = fmaf(w, cb.w, acc.w); }
                    if (cm & 8) { int ch = v + 1; float w = ewS[ch]; float4 cb = buf[ch];
                        acc.x = fmaf(w, cb.x, acc.x); acc.y = fmaf(w, cb.y, acc.y);
                        acc.z = fmaf(w, cb.z, acc.z); acc.w = fmaf(w, cb.w, acc.w); }
                    buf[v] = acc;
                }
                hi = lo;
                asm volatile("bar.sync 1, 64;" ::: "memory");
            }
            // down sweep (in place)
            int lo2 = lsS[1];
            for (int d = 1; d <= maxd; ++d) {
                int hi2 = lsS[d + 1];
                for (int i = lo2 + tid; i < hi2; i += 64) {
                    unsigned o = ordS[i];
                    int v = o & 0x3FFF;
                    int pd = (o >> 18) & 3;
                    int par = v + c_off[pd];
                    float w = ewS[v];
                    float c1 = 1.f - w * w;
                    float4 pv = buf[par];
                    float4 sv = buf[v];
                    sv.x = fmaf(w, pv.x, c1 * sv.x);
                    sv.y = fmaf(w, pv.y, c1 * sv.y);
                    sv.z = fmaf(w, pv.z, c1 * sv.z);
                    sv.w = fmaf(w, pv.w, c1 * sv.w);
                    buf[v] = sv;
                }
                lo2 = hi2;
                asm volatile("bar.sync 1, 64;" ::: "memory");
            }
        }
        __syncthreads();

        if (f == 0) {
            for (int v = tid; v < VN; v += NT) {
                float4 s = buf[v];
                buf[v] = make_float4(s.x / s.w, s.y / s.w, s.z / s.w, 1.f);
            }
            __syncthreads();
        }
    }

    // ---- loss partial: sum roi * |prob - AS| over this block's 3 channels ----
    const int* roiB = roi + (size_t)b * (H0_ * H0_);
    double aL = 0.0, aN = 0.0;
    for (int v = tid; v < VN; v += NT) {
        float4 s = buf[v];
        float ax = pr0[v] - s.x / s.w;
        float ay = pr0[v + VN] - s.y / s.w;
        float az = pr0[v + 2 * VN] - s.z / s.w;
        int y = v / WID, x = v - y * WID;
        float rv = (float)roiB[(y * 4) * H0_ + x * 4];
        aL += (double)(rv * (fabsf(ax) + fabsf(ay) + fabsf(az)));
        if (g == 0) aN += (double)rv;
    }
    sredL[tid] = aL; sredN[tid] = aN;
    __syncthreads();
    for (int s = 128; s > 0; s >>= 1) {
        if (tid < s) { sredL[tid] += sredL[tid + s]; sredN[tid] += sredN[tid + s]; }
        __syncthreads();
    }
    if (tid == 0) {
        g_partL[b * 7 + g] = sredL[0];
        if (g == 0) g_partN[b] = sredN[0];
    }
}

// ---------------- final loss ----------------
__global__ void loss_final_kernel(float* out) {
    if (threadIdx.x == 0 && blockIdx.x == 0) {
        double L = 0.0, N = 0.0;
        for (int i = 0; i < 56; i++) L += g_partL[i];
        for (int i = 0; i < B_; i++) N += g_partN[i];
        double res = (N > 0.0) ? L / ((N > 1.0) ? N : 1.0) : L;
        out[0] = (float)(0.4 * res);
    }
}

// ---------------- launch ----------------
extern "C" void kernel_launch(void* const* d_in, const int* in_sizes, int n_in,
                              void* d_out, int out_size) {
    (void)in_sizes; (void)n_in; (void)out_size;
    const float* preds = (const float*)d_in[0];
    const float* low = (const float*)d_in[1];
    const float* high = (const float*)d_in[2];
    const int* roi = (const int*)d_in[3];
    float* out = (float*)d_out;

    cudaFuncSetAttribute(build_kernel, cudaFuncAttributeMaxDynamicSharedMemorySize, BUILD_SMEM);
    cudaFuncSetAttribute(sweep_kernel, cudaFuncAttributeMaxDynamicSharedMemorySize, SWEEP_SMEM);

    resize_kernel<<<(B_ * 3 * VN + 255) / 256, 256>>>(low);
    softmax_kernel<<<(B_ * VN + 255) / 256, 256>>>(preds);
    build_kernel<<<16, 1024, BUILD_SMEM>>>(high);
    dim3 gs(7, B_);
    sweep_kernel<<<gs, 256, SWEEP_SMEM>>>(roi);
    loss_final_kernel<<<1, 1>>>(out);
}

// round 6
// speedup vs baseline: 2.0052x; 1.1146x over previous
#include <cuda_runtime.h>
#include <math.h>
#include <stdint.h>

#define VN 9216
#define EN 18240
#define WID 96
#define B_ 8
#define NC 21
#define H0_ 384
#define ROOTV 4656   /* grid center 48*96+48 — heuristic tree-center root */

// ---------------- global scratch ----------------
__device__ __align__(16) float g_low[B_ * 3 * VN];
__device__ float g_prob[B_ * NC * VN];
__device__ __align__(16) float g_w[16 * EN];  // edge weights per tree
__device__ float g_ew[16 * VN];               // indexed by node
__device__ unsigned g_ord32[16 * VN];         // rank -> v | childmask<<14 | pardir<<18
__device__ int g_tredge[16 * VN];
__device__ int g_levelstart[16 * 1024];
__device__ int g_maxd[16];
__device__ double g_partL[56];
__device__ double g_partN[B_];

__constant__ int c_off[4] = {-WID, WID, -1, 1};

__device__ __forceinline__ void edge_uv(int e, int& u, int& v) {
    if (e < 9120) { u = e; v = e + WID; }
    else { int t = e - 9120; int r = t / 95, c = t - r * 95; u = r * WID + c; v = u + 1; }
}

// ---------------- prep: antialiased bilinear resize 384->96 ----------------
__global__ void resize_kernel(const float* __restrict__ low) {
    int idx = blockIdx.x * blockDim.x + threadIdx.x;
    if (idx >= B_ * 3 * VN) return;
    int v = idx % VN;
    int bc = idx / VN;
    int oy = v / WID, ox = v - (v / WID) * WID;
    const float rw[8] = {0.125f, 0.375f, 0.625f, 0.875f, 0.875f, 0.625f, 0.375f, 0.125f};
    int iy0 = 4 * oy - 2, ix0 = 4 * ox - 2;
    float wy[8], wx[8], sy = 0.f, sx = 0.f;
#pragma unroll
    for (int j = 0; j < 8; j++) {
        int iy = iy0 + j;
        wy[j] = (iy >= 0 && iy < H0_) ? rw[j] : 0.f;
        sy += wy[j];
        int ix = ix0 + j;
        wx[j] = (ix >= 0 && ix < H0_) ? rw[j] : 0.f;
        sx += wx[j];
    }
    const float* src = low + (size_t)bc * (H0_ * H0_);
    float acc = 0.f;
#pragma unroll
    for (int j = 0; j < 8; j++) {
        if (wy[j] == 0.f) continue;
        const float* row = src + (iy0 + j) * H0_;
        float rs = 0.f;
#pragma unroll
        for (int k = 0; k < 8; k++) {
            if (wx[k] != 0.f) rs += wx[k] * row[ix0 + k];
        }
        acc += wy[j] * rs;
    }
    g_low[idx] = acc / (sy * sx);
}

// ---------------- prep: softmax ----------------
__global__ void softmax_kernel(const float* __restrict__ preds) {
    int idx = blockIdx.x * blockDim.x + threadIdx.x;
    if (idx >= B_ * VN) return;
    int b = idx / VN, v = idx - (idx / VN) * VN;
    const float* p = preds + (size_t)b * NC * VN + v;
    float vals[NC];
    float m = -3.4e38f;
#pragma unroll
    for (int c = 0; c < NC; c++) { vals[c] = p[(size_t)c * VN]; m = fmaxf(m, vals[c]); }
    float s = 0.f;
#pragma unroll
    for (int c = 0; c < NC; c++) { vals[c] = expf(vals[c] - m); s += vals[c]; }
    float inv = 1.f / s;
    float* o = g_prob + (size_t)b * NC * VN + v;
#pragma unroll
    for (int c = 0; c < NC; c++) o[(size_t)c * VN] = vals[c] * inv;
}

// ---------------- edge weights: 16 trees x 8 row-slabs, 96 threads each ----------------
__global__ void __launch_bounds__(96, 1)
edgew_kernel(const float* __restrict__ high) {
    int s = blockIdx.x;           // slab 0..7
    int t = blockIdx.y;           // tree 0..15
    int b = t >> 1, f = t & 1;
    const float* embed = f ? (high + (size_t)b * 256 * VN) : ((const float*)g_low + (size_t)b * 3 * VN);
    int C = f ? 256 : 3;
    float* wT = g_w + (size_t)t * EN;
    int tid = threadIdx.x;
    int t0 = tid % 24, band = tid / 24;
    int gb = s * 4 + band;        // global 3-row band 0..31
    int c0 = t0 * 4, r0 = gb * 3;
    bool hasR3 = (gb < 31);
    bool hasS = (t0 < 23);
    float aV[3][4], aH[3][4];
#pragma unroll
    for (int j = 0; j < 3; j++)
#pragma unroll
        for (int k = 0; k < 4; k++) { aV[j][k] = 0.f; aH[j][k] = 0.f; }
#pragma unroll 2
    for (int c = 0; c < C; ++c) {
        const float* pf = embed + (size_t)c * VN;
        const float4* p4 = (const float4*)pf;
        float4 q0 = p4[(r0 + 0) * 24 + t0];
        float4 q1 = p4[(r0 + 1) * 24 + t0];
        float4 q2 = p4[(r0 + 2) * 24 + t0];
        float4 q3 = hasR3 ? p4[(r0 + 3) * 24 + t0] : make_float4(0.f, 0.f, 0.f, 0.f);
        float rr[4][4];
        rr[0][0]=q0.x; rr[0][1]=q0.y; rr[0][2]=q0.z; rr[0][3]=q0.w;
        rr[1][0]=q1.x; rr[1][1]=q1.y; rr[1][2]=q1.z; rr[1][3]=q1.w;
        rr[2][0]=q2.x; rr[2][1]=q2.y; rr[2][2]=q2.z; rr[2][3]=q2.w;
        rr[3][0]=q3.x; rr[3][1]=q3.y; rr[3][2]=q3.z; rr[3][3]=q3.w;
        float s0 = 0.f, s1 = 0.f, s2 = 0.f;
        if (hasS) {
            s0 = pf[(r0 + 0) * WID + c0 + 4];
            s1 = pf[(r0 + 1) * WID + c0 + 4];
            s2 = pf[(r0 + 2) * WID + c0 + 4];
        }
        float ss[3] = {s0, s1, s2};
#pragma unroll
        for (int j = 0; j < 3; j++) {
#pragma unroll
            for (int k = 0; k < 4; k++) {
                float dv = rr[j][k] - rr[j + 1][k];
                aV[j][k] += dv * dv;
            }
#pragma unroll
            for (int k = 0; k < 3; k++) {
                float dh = rr[j][k] - rr[j][k + 1];
                aH[j][k] += dh * dh;
            }
            if (hasS) { float dh = rr[j][3] - ss[j]; aH[j][3] += dh * dh; }
        }
    }
#pragma unroll
    for (int j = 0; j < 3; j++) {
        int r = r0 + j;
        if (r < 95) {
#pragma unroll
            for (int k = 0; k < 4; k++) wT[r * WID + c0 + k] = aV[j][k];
        }
        int hb = 9120 + r * 95 + c0;
        wT[hb + 0] = aH[j][0]; wT[hb + 1] = aH[j][1]; wT[hb + 2] = aH[j][2];
        if (hasS) wT[hb + 3] = aH[j][3];
    }
}

// ---------------- MST + rooting + export ----------------
// smem layout:
//   [0,73728)        bestS u64[VN]      | post: qS u16[VN] @0, par16 u16[VN] @18432
//   [73728,146688)   wS float[EN]       (alive until export)
//   [146688,183552)  compS int[VN]      | post: lsS int[1024] @146688
//   [183552,220416)  linkS int[VN]      | post: adjS int[VN]
#define BUILD_SMEM 220416

extern "C" __global__ void __launch_bounds__(1024, 1)
mst_kernel() {
    extern __shared__ unsigned char sm[];
    int t = blockIdx.x;

    unsigned long long* bestS = (unsigned long long*)sm;
    float* wS = (float*)(sm + 73728);
    int* compS = (int*)(sm + 146688);
    int* linkS = (int*)(sm + 183552);
    unsigned short* qS = (unsigned short*)sm;
    unsigned short* par16 = (unsigned short*)(sm + 18432);
    int* lsS = (int*)(sm + 146688);
    int* adjS = (int*)(sm + 183552);

    __shared__ int sFlag, sCnt, sCur;
    int tid = threadIdx.x;
    const int NT = 1024;

    // ---- 0. load edge weights ----
    {
        float4* w4 = (float4*)wS;
        const float4* gw4 = (const float4*)(g_w + (size_t)t * EN);
        for (int i = tid; i < EN / 4; i += NT) w4[i] = gw4[i];
    }
    for (int v = tid; v < VN; v += NT) compS[v] = v;
    if (tid == 0) sCnt = 0;
    __syncthreads();

    // ---- 1. Boruvka, vertex-gather ((w_bits,e) keys == stable-Kruskal) ----
    for (int round = 0; round < 30; ++round) {
        for (int v = tid; v < VN; v += NT) bestS[v] = ~0ull;
        if (tid == 0) sFlag = 0;
        __syncthreads();
        for (int v = tid; v < VN; v += NT) {
            int cv = compS[v];
            int r = v / WID, c = v - r * WID;
            unsigned long long best = ~0ull;
            if (r > 0 && compS[v - WID] != cv) {
                int e = v - WID;
                unsigned long long k = ((unsigned long long)__float_as_uint(wS[e]) << 32) | (unsigned)e;
                if (k < best) best = k;
            }
            if (r < 95 && compS[v + WID] != cv) {
                int e = v;
                unsigned long long k = ((unsigned long long)__float_as_uint(wS[e]) << 32) | (unsigned)e;
                if (k < best) best = k;
            }
            if (c > 0 && compS[v - 1] != cv) {
                int e = 9120 + r * 95 + c - 1;
                unsigned long long k = ((unsigned long long)__float_as_uint(wS[e]) << 32) | (unsigned)e;
                if (k < best) best = k;
            }
            if (c < 95 && compS[v + 1] != cv) {
                int e = 9120 + r * 95 + c;
                unsigned long long k = ((unsigned long long)__float_as_uint(wS[e]) << 32) | (unsigned)e;
                if (k < best) best = k;
            }
            if (best != ~0ull) {
                if (round == 0) bestS[v] = best;
                else atomicMin(&bestS[cv], best);
                sFlag = 1;
            }
        }
        __syncthreads();
        if (!sFlag) break;
        for (int v = tid; v < VN; v += NT) {
            unsigned long long bk = bestS[v];
            int nl = v;
            if (bk != ~0ull) {
                int e = (int)(bk & 0xffffffffu);
                int u0, v0; edge_uv(e, u0, v0);
                int cu = compS[u0], cv = compS[v0];
                int d = (cu == v) ? cv : cu;
                nl = d;
                if (bestS[d] != bk || v < d) {
                    int p = atomicAdd(&sCnt, 1);
                    g_tredge[t * VN + p] = e;
                }
            }
            linkS[v] = nl;
        }
        __syncthreads();
        {   // break 2-cycles (only cycles possible under distinct keys)
            int nl[9]; int ki = 0;
            for (int v = tid; v < VN; v += NT, ++ki) {
                int l = linkS[v];
                nl[ki] = (l != v && linkS[l] == v && v < l) ? v : l;
            }
            __syncthreads();
            ki = 0;
            for (int v = tid; v < VN; v += NT, ++ki) linkS[v] = nl[ki];
            __syncthreads();
        }
        // per-thread root chase (bounded: link forest is acyclic after 2-cycle break)
        for (int v = tid; v < VN; v += NT) {
            int r = compS[v];
            int l = linkS[r];
            int guard = 0;
            while (l != r && guard < VN) { r = l; l = linkS[r]; guard++; }
            compS[v] = r;
        }
        __syncthreads();
    }
    __syncthreads();
    int nTree = sCnt;

    // ---- 2. tree adjacency masks (bit0:-96 bit1:+96 bit2:-1 bit3:+1) ----
    for (int v = tid; v < VN; v += NT) adjS[v] = 0;
    __syncthreads();
    for (int i = tid; i < nTree; i += NT) {
        int e = g_tredge[t * VN + i];
        int u, v; edge_uv(e, u, v);
        if (e < 9120) { atomicOr(&adjS[u], 2); atomicOr(&adjS[v], 1); }
        else { atomicOr(&adjS[u], 8); atomicOr(&adjS[v], 4); }
    }
    __syncthreads();

    // ---- 3. frontier BFS from grid-center root (root-invariant filter) ----
    if (tid == 0) {
        qS[0] = (unsigned short)ROOTV;
        par16[ROOTV] = 0xFFFFu;
        sCur = 1;
        lsS[0] = 0; lsS[1] = 1;
    }
    __syncthreads();
    int fs = 0, fe = 1, level = 0;
    while (level < 1000) {
        for (int i = fs + tid; i < fe; i += NT) {
            int v = qS[i];
            int par = par16[v];
            int delta = par - v;
            int pb = (delta == -WID) ? 1 : (delta == WID) ? 2 : (delta == -1) ? 4 : (delta == 1) ? 8 : 0;
            int m = adjS[v] & ~pb;
            while (m) {
                int dd = __ffs(m) - 1; m &= m - 1;
                int nb = v + c_off[dd];
                par16[nb] = (unsigned short)v;
                int pos = atomicAdd(&sCur, 1);
                qS[pos] = (unsigned short)nb;
            }
        }
        __syncthreads();
        int nc2 = sCur;
        __syncthreads();
        if (nc2 == fe) break;
        level++;
        if (tid == 0) lsS[level + 1] = nc2;
        fs = fe; fe = nc2;
    }
    int maxd = level;

    // ---- 4. export packed structure; ew from wS (tree edges ARE grid edges) ----
    for (int pos = tid; pos < VN; pos += NT) {
        int v = qS[pos];
        int par = par16[v];
        int m = adjS[v];
        int pardir = 0, cm = m;
        float ew = 0.f;
        if (par != 0xFFFF) {
            int delta = par - v;
            pardir = (delta == -WID) ? 0 : (delta == WID) ? 1 : (delta == -1) ? 2 : 3;
            cm = m & ~(1 << pardir);
            int mn = v < par ? v : par;
            int ad = delta < 0 ? -delta : delta;
            int e = (ad == WID) ? mn : 9120 + (mn / WID) * 95 + (mn - (mn / WID) * WID);
            ew = expf(-wS[e] * 0.5f);
        }
        g_ord32[t * VN + pos] = (unsigned)v | ((unsigned)cm << 14) | ((unsigned)pardir << 18);
        g_ew[t * VN + v] = ew;
    }
    for (int d = tid; d <= maxd + 1; d += NT) g_levelstart[t * 1024 + d] = lsS[d];
    if (tid == 0) g_maxd[t] = maxd;
}

// ---------------- sweep helpers ----------------
__device__ __forceinline__ void up_node(unsigned o, float4* buf, const float* ewS) {
    int v = o & 0x3FFF;
    int cm = (o >> 14) & 0xF;
    float4 acc = buf[v];
    if (cm & 1) { int ch = v - WID; float w = ewS[ch]; float4 cb = buf[ch];
        acc.x = fmaf(w, cb.x, acc.x); acc.y = fmaf(w, cb.y, acc.y);
        acc.z = fmaf(w, cb.z, acc.z); acc.w = fmaf(w, cb.w, acc.w); }
    if (cm & 2) { int ch = v + WID; float w = ewS[ch]; float4 cb = buf[ch];
        acc.x = fmaf(w, cb.x, acc.x); acc.y = fmaf(w, cb.y, acc.y);
        acc.z = fmaf(w, cb.z, acc.z); acc.w = fmaf(w, cb.w, acc.w); }
    if (cm & 4) { int ch = v - 1; float w = ewS[ch]; float4 cb = buf[ch];
        acc.x = fmaf(w, cb.x, acc.x); acc.y = fmaf(w, cb.y, acc.y);
        acc.z = fmaf(w, cb.z, acc.z); acc.w = fmaf(w, cb.w, acc.w); }
    if (cm & 8) { int ch = v + 1; float w = ewS[ch]; float4 cb = buf[ch];
        acc.x = fmaf(w, cb.x, acc.x); acc.y = fmaf(w, cb.y, acc.y);
        acc.z = fmaf(w, cb.z, acc.z); acc.w = fmaf(w, cb.w, acc.w); }
    buf[v] = acc;
}

__device__ __forceinline__ void down_node(unsigned o, float4* buf, const float* ewS) {
    int v = o & 0x3FFF;
    int pd = (o >> 18) & 3;
    int par = v + c_off[pd];
    float w = ewS[v];
    float c1 = 1.f - w * w;
    float4 pv = buf[par];
    float4 sv = buf[v];
    sv.x = fmaf(w, pv.x, c1 * sv.x);
    sv.y = fmaf(w, pv.y, c1 * sv.y);
    sv.z = fmaf(w, pv.z, c1 * sv.z);
    sv.w = fmaf(w, pv.w, c1 * sv.w);
    buf[v] = sv;
}

// ---------------- fused two-filter sweep + loss partial ----------------
// smem: buf float4[VN] @0 (147456) | ewS f32[VN] @147456 | ordS u32[VN] @184320
//       | lsS int[1024] @221184 ; loss sred doubles reuse ewS region at the end
#define SWEEP_SMEM 225280
#define OINV 0xFFFFFFFFu

extern "C" __global__ void __launch_bounds__(256, 1)
sweep_kernel(const int* __restrict__ roi) {
    extern __shared__ unsigned char sm[];
    float4* buf = (float4*)sm;
    float* ewS = (float*)(sm + 147456);
    unsigned* ordS = (unsigned*)(sm + 184320);
    int* lsS = (int*)(sm + 221184);
    double* sredL = (double*)(sm + 147456);
    double* sredN = (double*)(sm + 147456 + 2048);
    int g = blockIdx.x, b = blockIdx.y;
    int tid = threadIdx.x;
    const int NT = 256;

    const float* pr0 = g_prob + ((size_t)b * NC + 3 * g) * VN;
    for (int v = tid; v < VN; v += NT)
        buf[v] = make_float4(pr0[v], pr0[v + VN], pr0[v + 2 * VN], 1.f);

    for (int f = 0; f < 2; f++) {
        int t = b * 2 + f;
        int maxd = g_maxd[t];
        for (int v = tid; v < VN; v += NT) {
            ewS[v] = g_ew[t * VN + v];
            ordS[v] = g_ord32[t * VN + v];
        }
        for (int d = tid; d <= maxd + 1; d += NT) lsS[d] = g_levelstart[t * 1024 + d];
        __syncthreads();

        if (tid < 32) {
            int lane = tid;
            // ---- up sweep: levels maxd-1 .. 0; ls/ord prefetched across syncwarp ----
            int hi = lsS[maxd];
            int lo = lsS[maxd - 1];
            unsigned o0 = (lo + lane < hi) ? ordS[lo + lane] : OINV;
            for (int d = maxd - 1; d >= 0; --d) {
                int lo_next = (d > 0) ? lsS[d - 1] : 0;
                unsigned o_next = (d > 0 && lo_next + lane < lo) ? ordS[lo_next + lane] : OINV;
                if (o0 != OINV) up_node(o0, buf, ewS);
                for (int i = lo + lane + 32; i < hi; i += 32) up_node(ordS[i], buf, ewS);
                __syncwarp(0xFFFFFFFFu);
                hi = lo; lo = lo_next; o0 = o_next;
            }
            // ---- down sweep: levels 1 .. maxd (in place) ----
            int lo2 = lsS[1];
            int hi2 = lsS[2];
            o0 = (lo2 + lane < hi2) ? ordS[lo2 + lane] : OINV;
            for (int d = 1; d <= maxd; ++d) {
                int hi_next = (d < maxd) ? lsS[d + 2] : 0;
                unsigned o_next = (d < maxd && hi2 + lane < hi_next) ? ordS[hi2 + lane] : OINV;
                if (o0 != OINV) down_node(o0, buf, ewS);
                for (int i = lo2 + lane + 32; i < hi2; i += 32) down_node(ordS[i], buf, ewS);
                __syncwarp(0xFFFFFFFFu);
                lo2 = hi2; hi2 = hi_next; o0 = o_next;
            }
        }
        __syncthreads();

        if (f == 0) {
            for (int v = tid; v < VN; v += NT) {
                float4 s = buf[v];
                buf[v] = make_float4(s.x / s.w, s.y / s.w, s.z / s.w, 1.f);
            }
            __syncthreads();
        }
    }

    // ---- loss partial: sum roi * |prob - AS| over this block's 3 channels ----
    const int* roiB = roi + (size_t)b * (H0_ * H0_);
    double aL = 0.0, aN = 0.0;
    for (int v = tid; v < VN; v += NT) {
        float4 s = buf[v];
        float ax = pr0[v] - s.x / s.w;
        float ay = pr0[v + VN] - s.y / s.w;
        float az = pr0[v + 2 * VN] - s.z / s.w;
        int y = v / WID, x = v - y * WID;
        float rv = (float)roiB[(y * 4) * H0_ + x * 4];
        aL += (double)(rv * (fabsf(ax) + fabsf(ay) + fabsf(az)));
        if (g == 0) aN += (double)rv;
    }
    sredL[tid] = aL; sredN[tid] = aN;
    __syncthreads();
    for (int s = 128; s > 0; s >>= 1) {
        if (tid < s) { sredL[tid] += sredL[tid + s]; sredN[tid] += sredN[tid + s]; }
        __syncthreads();
    }
    if (tid == 0) {
        g_partL[b * 7 + g] = sredL[0];
        if (g == 0) g_partN[b] = sredN[0];
    }
}

// ---------------- final loss ----------------
__global__ void loss_final_kernel(float* out) {
    if (threadIdx.x == 0 && blockIdx.x == 0) {
        double L = 0.0, N = 0.0;
        for (int i = 0; i < 56; i++) L += g_partL[i];
        for (int i = 0; i < B_; i++) N += g_partN[i];
        double res = (N > 0.0) ? L / ((N > 1.0) ? N : 1.0) : L;
        out[0] = (float)(0.4 * res);
    }
}

// ---------------- launch ----------------
extern "C" void kernel_launch(void* const* d_in, const int* in_sizes, int n_in,
                              void* d_out, int out_size) {
    (void)in_sizes; (void)n_in; (void)out_size;
    const float* preds = (const float*)d_in[0];
    const float* low = (const float*)d_in[1];
    const float* high = (const float*)d_in[2];
    const int* roi = (const int*)d_in[3];
    float* out = (float*)d_out;

    cudaFuncSetAttribute(mst_kernel, cudaFuncAttributeMaxDynamicSharedMemorySize, BUILD_SMEM);
    cudaFuncSetAttribute(sweep_kernel, cudaFuncAttributeMaxDynamicSharedMemorySize, SWEEP_SMEM);

    resize_kernel<<<(B_ * 3 * VN + 255) / 256, 256>>>(low);
    softmax_kernel<<<(B_ * VN + 255) / 256, 256>>>(preds);
    dim3 ge(8, 16);
    edgew_kernel<<<ge, 96>>>(high);
    mst_kernel<<<16, 1024, BUILD_SMEM>>>();
    dim3 gs(7, B_);
    sweep_kernel<<<gs, 256, SWEEP_SMEM>>>(roi);
    loss_final_kernel<<<1, 1>>>(out);
}